// round 2
// baseline (speedup 1.0000x reference)
#include <cuda_runtime.h>
#include <cuda_bf16.h>
#include <math.h>

#define KS    11
#define HALO  5
#define TW    128   // tile width (outputs)
#define TH    32    // tile height (outputs)
#define TSTR  139   // smem row stride (139 mod 32 = 11, gcd(11,32)=1 -> conflict-free)
#define IMG   512

__device__ float g_w[KS];

// Tiny pre-kernel: compute normalized 1D Gaussian weights from sigma.
__global__ void gb_weights_kernel(const float* __restrict__ sigma) {
    if (threadIdx.x == 0) {
        float s = fabsf(sigma[0]) + 1e-6f;
        float inv2s2 = 1.0f / (2.0f * s * s);
        float w[KS];
        float sum = 0.0f;
        #pragma unroll
        for (int i = 0; i < KS; i++) {
            float r = (float)i - (float)(KS - 1) * 0.5f;
            w[i] = expf(-(r * r) * inv2s2);
            sum += w[i];
        }
        float inv = 1.0f / sum;
        #pragma unroll
        for (int i = 0; i < KS; i++) g_w[i] = w[i] * inv;
    }
}

__device__ __forceinline__ int reflect_lo(int i) { return i < 0 ? -i : i; }
__device__ __forceinline__ int reflect_hi(int i) { return i > (IMG - 1) ? 2 * (IMG - 1) - i : i; }

__global__ void __launch_bounds__(256)
gb_blur_kernel(const float* __restrict__ x, float* __restrict__ out) {
    __shared__ float tmp[TH * TSTR];   // vertically-blurred intermediate, halo width 138

    const int tid   = threadIdx.x;
    const int plane = blockIdx.z;                 // b*C + c
    const int x0    = blockIdx.x * TW;
    const int y0    = blockIdx.y * TH;

    const float* __restrict__ base = x + (size_t)plane * (IMG * IMG);

    // Load weights into registers (broadcast loads, L1-resident after first block).
    float w[KS];
    #pragma unroll
    for (int k = 0; k < KS; k++) w[k] = __ldg(&g_w[k]);

    // ---------------- Vertical pass: global -> smem ----------------
    // One thread per halo column (138 columns). Coalesced: warp lanes read
    // consecutive x. Sliding 11-tap window down the column.
    if (tid < TW + 2 * HALO) {
        int cx = x0 - HALO + tid;
        cx = reflect_hi(reflect_lo(cx));
        const float* __restrict__ col = base + cx;

        float win[KS];
        #pragma unroll
        for (int i = 0; i < KS - 1; i++) {
            int y = y0 - HALO + i;          // in [-5, 484]: only low reflect possible
            y = reflect_lo(y);
            win[i] = __ldg(col + y * IMG);
        }

        #pragma unroll
        for (int r = 0; r < TH; r++) {
            int y = y0 + HALO + r;          // in [5, 516]: only high reflect possible
            y = reflect_hi(y);
            win[(r + KS - 1) % KS] = __ldg(col + y * IMG);

            float acc = 0.0f;
            #pragma unroll
            for (int k = 0; k < KS; k++)
                acc = fmaf(win[(r + k) % KS], w[k], acc);

            tmp[r * TSTR + tid] = acc;
        }
    }
    __syncthreads();

    // ---------------- Horizontal pass: smem -> global ----------------
    // row = tid % 32 (warp lanes hit 32 distinct rows -> stride-139 gives
    // conflict-free banks), 8 segments of 16 outputs each.
    const int row = tid & 31;
    const int seg = tid >> 5;            // 0..7
    const int s0  = seg * 16;

    const float* __restrict__ trow = tmp + row * TSTR;

    float win[KS];
    #pragma unroll
    for (int i = 0; i < KS - 1; i++) win[i] = trow[s0 + i];

    float res[16];
    #pragma unroll
    for (int j = 0; j < 16; j++) {
        win[(j + KS - 1) % KS] = trow[s0 + (KS - 1) + j];
        float acc = 0.0f;
        #pragma unroll
        for (int k = 0; k < KS; k++)
            acc = fmaf(win[(j + k) % KS], w[k], acc);
        res[j] = acc;
    }

    float4* __restrict__ o = reinterpret_cast<float4*>(
        out + (size_t)plane * (IMG * IMG) + (size_t)(y0 + row) * IMG + x0 + s0);
    #pragma unroll
    for (int v = 0; v < 4; v++)
        o[v] = make_float4(res[4 * v + 0], res[4 * v + 1], res[4 * v + 2], res[4 * v + 3]);
}

extern "C" void kernel_launch(void* const* d_in, const int* in_sizes, int n_in,
                              void* d_out, int out_size) {
    const float* x     = (const float*)d_in[0];   // (16, 64, 512, 512) fp32
    const float* sigma = (const float*)d_in[1];   // (1,) fp32
    float* out = (float*)d_out;

    gb_weights_kernel<<<1, 32>>>(sigma);

    dim3 grid(IMG / TW, IMG / TH, 16 * 64);       // (4, 16, 1024)
    gb_blur_kernel<<<grid, 256>>>(x, out);
}